// round 8
// baseline (speedup 1.0000x reference)
#include <cuda_runtime.h>
#include <cuda_bf16.h>
#include <math.h>
#include <stdint.h>

#define C_IN   256
#define C_B    64
#define K_TAP  27
#define N_MAX  200000
#define BN_EPS 1e-3f

// ---------------- scratch (device globals; no allocation) ----------------
__device__ float g_h1[(size_t)N_MAX * C_B];   // conv1x1a raw
__device__ float g_h2[(size_t)N_MAX * C_B];   // octree conv raw
__device__ float g_h3[(size_t)N_MAX * C_IN];  // conv1x1b raw

__device__ __nv_bfloat16 g_h1h[(size_t)N_MAX * C_B];  // act1 hi
__device__ __nv_bfloat16 g_h1l[(size_t)N_MAX * C_B];  // act1 lo
__device__ __nv_bfloat16 g_w3h[K_TAP * C_B * C_B];    // w3 [k][c][d] hi
__device__ __nv_bfloat16 g_w3l[K_TAP * C_B * C_B];    // lo

__device__ float g_sum1[C_B],  g_sq1[C_B],  g_a1[C_B],  g_c1[C_B];
__device__ float g_sum2[C_B],  g_sq2[C_B],  g_a2[C_B],  g_c2[C_B];
__device__ float g_sum3[C_IN], g_sq3[C_IN], g_a3[C_IN], g_c3[C_IN];

__device__ __forceinline__ float gelu_exact(float x) {
    return 0.5f * x * (1.0f + erff(x * 0.70710678118654752440f));
}

// ---------------- stats reset ----------------
__global__ void zero_stats_kernel() {
    int t = threadIdx.x;
    if (t < C_B)  { g_sum1[t] = 0.f; g_sq1[t] = 0.f; g_sum2[t] = 0.f; g_sq2[t] = 0.f; }
    if (t < C_IN) { g_sum3[t] = 0.f; g_sq3[t] = 0.f; }
}

// ---------------- GEMM1: h1 = data[N,256] @ w1[256,64] (fp32) ----------------
__global__ void gemm1_kernel(const float* __restrict__ data,
                             const float* __restrict__ w1) {
    __shared__ float sA[64][36];
    __shared__ float sB[32][64];
    const int tid = threadIdx.x;
    const int tx = tid & 15, ty = tid >> 4;
    const int row0 = blockIdx.x * 64;

    const int lr = tid >> 2;
    const int lk = (tid & 3) * 8;
    const int br = tid >> 3;
    const int bc = (tid & 7) * 8;

    float acc[4][4] = {};

    for (int kb = 0; kb < C_IN; kb += 32) {
        const float4* ap = (const float4*)(data + (size_t)(row0 + lr) * C_IN + kb + lk);
        float4 a0 = ap[0], a1 = ap[1];
        *(float4*)&sA[lr][lk]     = a0;
        *(float4*)&sA[lr][lk + 4] = a1;

        const float4* bp = (const float4*)(w1 + (size_t)(kb + br) * C_B + bc);
        float4 b0 = bp[0], b1 = bp[1];
        *(float4*)&sB[br][bc]     = b0;
        *(float4*)&sB[br][bc + 4] = b1;
        __syncthreads();

        #pragma unroll
        for (int kk = 0; kk < 32; kk += 4) {
            float4 av[4];
            #pragma unroll
            for (int i = 0; i < 4; i++) av[i] = *(const float4*)&sA[ty * 4 + i][kk];
            #pragma unroll
            for (int u = 0; u < 4; u++) {
                float4 w = *(const float4*)&sB[kk + u][tx * 4];
                #pragma unroll
                for (int i = 0; i < 4; i++) {
                    float a = (&av[i].x)[u];
                    acc[i][0] = fmaf(a, w.x, acc[i][0]);
                    acc[i][1] = fmaf(a, w.y, acc[i][1]);
                    acc[i][2] = fmaf(a, w.z, acc[i][2]);
                    acc[i][3] = fmaf(a, w.w, acc[i][3]);
                }
            }
        }
        __syncthreads();
    }

    #pragma unroll
    for (int i = 0; i < 4; i++) {
        *(float4*)&g_h1[(size_t)(row0 + ty * 4 + i) * C_B + tx * 4] =
            make_float4(acc[i][0], acc[i][1], acc[i][2], acc[i][3]);
    }
}

// ---------------- per-channel stats ----------------
template<int CC>
__device__ __forceinline__ void stats_body(const float* __restrict__ x, int n,
                                           float* __restrict__ sums,
                                           float* __restrict__ sqs) {
    __shared__ float sm[256], qm[256];
    const int tid = threadIdx.x;
    const int col = tid % CC;
    const int rid = tid / CC;
    const int rpt = 256 / CC;

    long long rows_per_blk = (n + gridDim.x - 1) / gridDim.x;
    long long r0 = (long long)blockIdx.x * rows_per_blk;
    long long r1 = r0 + rows_per_blk; if (r1 > n) r1 = n;

    float s = 0.f, q = 0.f;
    for (long long r = r0 + rid; r < r1; r += rpt) {
        float v = x[r * CC + col];
        s += v; q += v * v;
    }
    sm[tid] = s; qm[tid] = q;
    __syncthreads();
    for (int off = 128; off >= CC; off >>= 1) {
        if (tid < off) { sm[tid] += sm[tid + off]; qm[tid] += qm[tid + off]; }
        __syncthreads();
    }
    if (tid < CC) {
        atomicAdd(&sums[tid], sm[tid]);
        atomicAdd(&sqs[tid],  qm[tid]);
    }
}

__global__ void stats1_kernel(int n) { stats_body<C_B >(g_h1, n, g_sum1, g_sq1); }
__global__ void stats2_kernel(int n) { stats_body<C_B >(g_h2, n, g_sum2, g_sq2); }
__global__ void stats3_kernel(int n) { stats_body<C_IN>(g_h3, n, g_sum3, g_sq3); }

// ---------------- BN finalize ----------------
__device__ __forceinline__ void bnfin_body(const float* sums, const float* sqs,
                                           const float* __restrict__ g,
                                           const float* __restrict__ b,
                                           float* a, float* c, float inv_n) {
    int t = threadIdx.x;
    float m = sums[t] * inv_n;
    float v = sqs[t] * inv_n - m * m;
    if (v < 0.f) v = 0.f;
    float s = g[t] * rsqrtf(v + BN_EPS);
    a[t] = s;
    c[t] = b[t] - m * s;
}
__global__ void bnfin1_kernel(const float* __restrict__ g, const float* __restrict__ b, float inv_n)
{ bnfin_body(g_sum1, g_sq1, g, b, g_a1, g_c1, inv_n); }
__global__ void bnfin2_kernel(const float* __restrict__ g, const float* __restrict__ b, float inv_n)
{ bnfin_body(g_sum2, g_sq2, g, b, g_a2, g_c2, inv_n); }
__global__ void bnfin3_kernel(const float* __restrict__ g, const float* __restrict__ b, float inv_n)
{ bnfin_body(g_sum3, g_sq3, g, b, g_a3, g_c3, inv_n); }

// ---------------- act1: BN+GELU, write bf16 hi/lo split ----------------
__global__ void act1_split_kernel(long long total) {
    long long i = ((long long)blockIdx.x * blockDim.x + threadIdx.x) * 4;
    if (i >= total) return;
    float4 v = *(const float4*)&g_h1[i];
    int c = (int)(i & (C_B - 1));
    float x0 = gelu_exact(fmaf(g_a1[c],     v.x, g_c1[c]));
    float x1 = gelu_exact(fmaf(g_a1[c + 1], v.y, g_c1[c + 1]));
    float x2 = gelu_exact(fmaf(g_a1[c + 2], v.z, g_c1[c + 2]));
    float x3 = gelu_exact(fmaf(g_a1[c + 3], v.w, g_c1[c + 3]));

    __nv_bfloat16 h0 = __float2bfloat16(x0), h1 = __float2bfloat16(x1);
    __nv_bfloat16 h2 = __float2bfloat16(x2), h3 = __float2bfloat16(x3);
    __nv_bfloat16 l0 = __float2bfloat16(x0 - __bfloat162float(h0));
    __nv_bfloat16 l1 = __float2bfloat16(x1 - __bfloat162float(h1));
    __nv_bfloat16 l2 = __float2bfloat16(x2 - __bfloat162float(h2));
    __nv_bfloat16 l3 = __float2bfloat16(x3 - __bfloat162float(h3));

    ushort4 ph = make_ushort4(*(unsigned short*)&h0, *(unsigned short*)&h1,
                              *(unsigned short*)&h2, *(unsigned short*)&h3);
    ushort4 pl = make_ushort4(*(unsigned short*)&l0, *(unsigned short*)&l1,
                              *(unsigned short*)&l2, *(unsigned short*)&l3);
    *(ushort4*)((unsigned short*)g_h1h + i) = ph;
    *(ushort4*)((unsigned short*)g_h1l + i) = pl;
}

// ---------------- w3 split (keep [k][c][d] layout) ----------------
__global__ void w3_split_kernel(const float* __restrict__ w3) {
    int i = blockIdx.x * blockDim.x + threadIdx.x;
    if (i >= K_TAP * C_B * C_B) return;
    float v = w3[i];
    __nv_bfloat16 h = __float2bfloat16(v);
    __nv_bfloat16 l = __float2bfloat16(v - __bfloat162float(h));
    g_w3h[i] = h;
    g_w3l[i] = l;
}

// ============== octree conv via mma.sync (HMMA bf16, hi/lo split) ==============
// h2[128,64] per CTA; A = gathered act1 rows (bf16 hi/lo), B = w3[k] as [c][d].
// Warp tile 32x32 (2 M-tiles x 4 N-tiles). 3 split terms: AhWh + AhWl + AlWh.

#define SROW 72           // smem row stride in bf16 elems (144 B) - bank-conflict free
#define OFF_IDX 0                                  // 27*128 ints = 13824 B
#define OFF_AH  13824                              // 128*144 = 18432 B
#define OFF_AL  (OFF_AH + 128 * 144)               // 18432 B
#define OFF_WH  (OFF_AL + 128 * 144)               // 64*144 = 9216 B
#define OFF_WL  (OFF_WH + 64 * 144)                // 9216 B
#define OCT_SMEM (OFF_WL + 64 * 144)               // 69120 B

__device__ __forceinline__ uint32_t smem_u32(const void* p) {
    uint32_t a;
    asm("{ .reg .u64 t; cvta.to.shared.u64 t, %1; cvt.u32.u64 %0, t; }"
        : "=r"(a) : "l"(p));
    return a;
}
__device__ __forceinline__ void ldsm_x4(uint32_t* r, uint32_t addr) {
    asm volatile("ldmatrix.sync.aligned.m8n8.x4.shared.b16 {%0,%1,%2,%3}, [%4];"
                 : "=r"(r[0]), "=r"(r[1]), "=r"(r[2]), "=r"(r[3]) : "r"(addr));
}
__device__ __forceinline__ void ldsm_x4_t(uint32_t* r, uint32_t addr) {
    asm volatile("ldmatrix.sync.aligned.m8n8.x4.trans.shared.b16 {%0,%1,%2,%3}, [%4];"
                 : "=r"(r[0]), "=r"(r[1]), "=r"(r[2]), "=r"(r[3]) : "r"(addr));
}
__device__ __forceinline__ void mma_bf16(float* d, const uint32_t* a, const uint32_t* b) {
    asm volatile(
        "mma.sync.aligned.m16n8k16.row.col.f32.bf16.bf16.f32 "
        "{%0,%1,%2,%3}, {%4,%5,%6,%7}, {%8,%9}, {%0,%1,%2,%3};"
        : "+f"(d[0]), "+f"(d[1]), "+f"(d[2]), "+f"(d[3])
        : "r"(a[0]), "r"(a[1]), "r"(a[2]), "r"(a[3]), "r"(b[0]), "r"(b[1]));
}

__global__ void __launch_bounds__(256) octconv_mma_kernel(const int* __restrict__ neigh,
                                                          int n) {
    extern __shared__ char smem[];
    const uint32_t sb = smem_u32(smem);
    const int tid = threadIdx.x;
    const int wid = tid >> 5, lane = tid & 31;
    const int wr = wid & 3, wc = wid >> 2;       // warp row band (32), col band (32)
    const int row0 = blockIdx.x * 128;

    int* sIdx = (int*)(smem + OFF_IDX);
    const uint4* h1h4 = (const uint4*)g_h1h;
    const uint4* h1l4 = (const uint4*)g_h1l;
    const uint4* w3h4 = (const uint4*)g_w3h;
    const uint4* w3l4 = (const uint4*)g_w3l;

    // stage gather indices: sIdx[k][r]
    for (int i = tid; i < K_TAP * 128; i += 256) {
        int r = i / K_TAP, k = i - r * K_TAP;
        int nr = row0 + r;
        sIdx[k * 128 + r] = (nr < n) ? neigh[(size_t)nr * K_TAP + k] : 0;
    }
    __syncthreads();

    // stage tap 0
    {
        const int* idx = sIdx;
        #pragma unroll
        for (int j = 0; j < 4; j++) {
            int cid = tid + 256 * j;              // 0..1023
            int r = cid >> 3, q = cid & 7;
            int gr = idx[r];
            *(uint4*)(smem + OFF_AH + r * 144 + q * 16) = h1h4[(size_t)gr * 8 + q];
            *(uint4*)(smem + OFF_AL + r * 144 + q * 16) = h1l4[(size_t)gr * 8 + q];
        }
        #pragma unroll
        for (int j = 0; j < 2; j++) {
            int cid = tid + 256 * j;              // 0..511
            int r = cid >> 3, q = cid & 7;
            *(uint4*)(smem + OFF_WH + r * 144 + q * 16) = w3h4[cid];
            *(uint4*)(smem + OFF_WL + r * 144 + q * 16) = w3l4[cid];
        }
    }
    __syncthreads();

    float acc[2][4][4];
    #pragma unroll
    for (int mt = 0; mt < 2; mt++)
        #pragma unroll
        for (int nt = 0; nt < 4; nt++)
            #pragma unroll
            for (int q = 0; q < 4; q++) acc[mt][nt][q] = 0.f;

    // per-lane ldmatrix address components
    const uint32_t aOff = (uint32_t)((wr * 32 + (lane & 15)) * 144 + (lane >> 4) * 16);
    const uint32_t bOff = (uint32_t)((lane & 15) * 144 + (wc * 32 + (lane >> 4) * 8) * 2);

    for (int k = 0; k < K_TAP; k++) {
        // prefetch tap k+1 gather into registers
        uint4 pAh[4], pAl[4], pWh[2], pWl[2];
        if (k + 1 < K_TAP) {
            const int* idx = sIdx + (k + 1) * 128;
            #pragma unroll
            for (int j = 0; j < 4; j++) {
                int cid = tid + 256 * j;
                int r = cid >> 3, q = cid & 7;
                int gr = idx[r];
                pAh[j] = h1h4[(size_t)gr * 8 + q];
                pAl[j] = h1l4[(size_t)gr * 8 + q];
            }
            #pragma unroll
            for (int j = 0; j < 2; j++) {
                int cid = tid + 256 * j;
                pWh[j] = w3h4[(size_t)(k + 1) * 512 + cid];
                pWl[j] = w3l4[(size_t)(k + 1) * 512 + cid];
            }
        }

        // compute on current buffer
        #pragma unroll
        for (int ks = 0; ks < 4; ks++) {
            uint32_t ah[2][4], al[2][4], bh[2][4], bl[2][4];
            #pragma unroll
            for (int mt = 0; mt < 2; mt++) {
                uint32_t ad = sb + OFF_AH + aOff + (uint32_t)(mt * 16 * 144 + ks * 32);
                ldsm_x4(ah[mt], ad);
                ldsm_x4(al[mt], ad + (OFF_AL - OFF_AH));
            }
            #pragma unroll
            for (int nt2 = 0; nt2 < 2; nt2++) {
                uint32_t bd = sb + OFF_WH + bOff + (uint32_t)(ks * 16 * 144 + nt2 * 32);
                ldsm_x4_t(bh[nt2], bd);
                ldsm_x4_t(bl[nt2], bd + (OFF_WL - OFF_WH));
            }
            #pragma unroll
            for (int mt = 0; mt < 2; mt++) {
                #pragma unroll
                for (int nt = 0; nt < 4; nt++) {
                    const uint32_t* ph = &bh[nt >> 1][(nt & 1) * 2];
                    const uint32_t* pl = &bl[nt >> 1][(nt & 1) * 2];
                    mma_bf16(acc[mt][nt], ah[mt], ph);
                    mma_bf16(acc[mt][nt], ah[mt], pl);
                    mma_bf16(acc[mt][nt], al[mt], ph);
                }
            }
        }
        __syncthreads();

        // store prefetched tap k+1
        if (k + 1 < K_TAP) {
            #pragma unroll
            for (int j = 0; j < 4; j++) {
                int cid = tid + 256 * j;
                int r = cid >> 3, q = cid & 7;
                *(uint4*)(smem + OFF_AH + r * 144 + q * 16) = pAh[j];
                *(uint4*)(smem + OFF_AL + r * 144 + q * 16) = pAl[j];
            }
            #pragma unroll
            for (int j = 0; j < 2; j++) {
                int cid = tid + 256 * j;
                int r = cid >> 3, q = cid & 7;
                *(uint4*)(smem + OFF_WH + r * 144 + q * 16) = pWh[j];
                *(uint4*)(smem + OFF_WL + r * 144 + q * 16) = pWl[j];
            }
            __syncthreads();
        }
    }

    // epilogue: write acc to g_h2
    #pragma unroll
    for (int mt = 0; mt < 2; mt++) {
        int r0 = row0 + wr * 32 + mt * 16 + (lane >> 2);
        #pragma unroll
        for (int nt = 0; nt < 4; nt++) {
            int col = wc * 32 + nt * 8 + (lane & 3) * 2;
            if (r0 < n)
                *(float2*)&g_h2[(size_t)r0 * C_B + col] =
                    make_float2(acc[mt][nt][0], acc[mt][nt][1]);
            if (r0 + 8 < n)
                *(float2*)&g_h2[(size_t)(r0 + 8) * C_B + col] =
                    make_float2(acc[mt][nt][2], acc[mt][nt][3]);
        }
    }
}

// ---------------- GEMM2: h3 = act2(h2)[N,64] @ w2[64,256] (fp32, act fused) ----------------
__global__ void gemm2_kernel(const float* __restrict__ w2) {
    __shared__ float sA[64][36];
    __shared__ float sB[32][256];
    const int tid = threadIdx.x;
    const int tx = tid & 15, ty = tid >> 4;
    const int row0 = blockIdx.x * 64;

    float acc[4][16] = {};

    for (int cb = 0; cb < C_B; cb += 32) {
        {
            int lr = tid >> 2;
            int cofs = (tid & 3) * 8;
            const float* src = g_h2 + (size_t)(row0 + lr) * C_B + cb + cofs;
            float4 v0 = *(const float4*)(src);
            float4 v1 = *(const float4*)(src + 4);
            int c = cb + cofs;
            v0.x = gelu_exact(fmaf(g_a2[c],     v0.x, g_c2[c]));
            v0.y = gelu_exact(fmaf(g_a2[c + 1], v0.y, g_c2[c + 1]));
            v0.z = gelu_exact(fmaf(g_a2[c + 2], v0.z, g_c2[c + 2]));
            v0.w = gelu_exact(fmaf(g_a2[c + 3], v0.w, g_c2[c + 3]));
            v1.x = gelu_exact(fmaf(g_a2[c + 4], v1.x, g_c2[c + 4]));
            v1.y = gelu_exact(fmaf(g_a2[c + 5], v1.y, g_c2[c + 5]));
            v1.z = gelu_exact(fmaf(g_a2[c + 6], v1.z, g_c2[c + 6]));
            v1.w = gelu_exact(fmaf(g_a2[c + 7], v1.w, g_c2[c + 7]));
            *(float4*)&sA[lr][cofs]     = v0;
            *(float4*)&sA[lr][cofs + 4] = v1;
        }
        {
            const float4* wp = (const float4*)(w2 + (size_t)cb * C_IN);
            #pragma unroll
            for (int j = 0; j < 8; j++)
                ((float4*)sB)[tid + 256 * j] = wp[tid + 256 * j];
        }
        __syncthreads();

        #pragma unroll
        for (int c = 0; c < 32; c += 4) {
            float4 av[4];
            #pragma unroll
            for (int i = 0; i < 4; i++) av[i] = *(const float4*)&sA[ty * 4 + i][c];
            #pragma unroll
            for (int u = 0; u < 4; u++) {
                #pragma unroll
                for (int j4 = 0; j4 < 4; j4++) {
                    float4 w = *(const float4*)&sB[c + u][tx * 4 + j4 * 64];
                    #pragma unroll
                    for (int i = 0; i < 4; i++) {
                        float a = (&av[i].x)[u];
                        acc[i][j4 * 4 + 0] = fmaf(a, w.x, acc[i][j4 * 4 + 0]);
                        acc[i][j4 * 4 + 1] = fmaf(a, w.y, acc[i][j4 * 4 + 1]);
                        acc[i][j4 * 4 + 2] = fmaf(a, w.z, acc[i][j4 * 4 + 2]);
                        acc[i][j4 * 4 + 3] = fmaf(a, w.w, acc[i][j4 * 4 + 3]);
                    }
                }
            }
        }
        __syncthreads();
    }

    #pragma unroll
    for (int i = 0; i < 4; i++) {
        #pragma unroll
        for (int j4 = 0; j4 < 4; j4++) {
            *(float4*)&g_h3[(size_t)(row0 + ty * 4 + i) * C_IN + tx * 4 + j4 * 64] =
                make_float4(acc[i][j4 * 4 + 0], acc[i][j4 * 4 + 1],
                            acc[i][j4 * 4 + 2], acc[i][j4 * 4 + 3]);
        }
    }
}

// ---------------- epilogue: out = elu(bn3(h3) + data) ----------------
__global__ void final_kernel(const float* __restrict__ data,
                             float* __restrict__ out, long long total) {
    long long i = ((long long)blockIdx.x * blockDim.x + threadIdx.x) * 4;
    if (i >= total) return;
    float4 h = *(const float4*)&g_h3[i];
    float4 d = *(const float4*)&data[i];
    int c = (int)(i & (C_IN - 1));
    float x;
    x = fmaf(g_a3[c],     h.x, g_c3[c]) + d.x; h.x = x > 0.f ? x : expm1f(x);
    x = fmaf(g_a3[c + 1], h.y, g_c3[c + 1]) + d.y; h.y = x > 0.f ? x : expm1f(x);
    x = fmaf(g_a3[c + 2], h.z, g_c3[c + 2]) + d.z; h.z = x > 0.f ? x : expm1f(x);
    x = fmaf(g_a3[c + 3], h.w, g_c3[c + 3]) + d.w; h.w = x > 0.f ? x : expm1f(x);
    *(float4*)&out[i] = h;
}

// ---------------- launch ----------------
extern "C" void kernel_launch(void* const* d_in, const int* in_sizes, int n_in,
                              void* d_out, int out_size) {
    const float* data  = (const float*)d_in[0];
    const int*   neigh = (const int*)d_in[1];
    const float* w1 = (const float*)d_in[2];
    const float* g1 = (const float*)d_in[3];
    const float* b1 = (const float*)d_in[4];
    const float* w3 = (const float*)d_in[5];
    const float* g3 = (const float*)d_in[6];
    const float* b3 = (const float*)d_in[7];
    const float* w2 = (const float*)d_in[8];
    const float* g2 = (const float*)d_in[9];
    const float* b2 = (const float*)d_in[10];
    float* out = (float*)d_out;

    const int n = in_sizes[0] / C_IN;
    const float inv_n = 1.0f / (float)n;
    const int nblk64 = n / 64;
    const int nblk128 = (n + 127) / 128;
    const long long tot_b = (long long)n * C_B;
    const long long tot_c = (long long)n * C_IN;

    cudaFuncSetAttribute(octconv_mma_kernel,
                         cudaFuncAttributeMaxDynamicSharedMemorySize, OCT_SMEM);

    zero_stats_kernel<<<1, 256>>>();
    w3_split_kernel<<<(K_TAP * C_B * C_B + 255) / 256, 256>>>(w3);

    gemm1_kernel<<<nblk64, 256>>>(data, w1);
    stats1_kernel<<<512, 256>>>(n);
    bnfin1_kernel<<<1, C_B>>>(g1, b1, inv_n);
    act1_split_kernel<<<(int)((tot_b / 4 + 255) / 256), 256>>>(tot_b);

    octconv_mma_kernel<<<nblk128, 256, OCT_SMEM>>>(neigh, n);
    stats2_kernel<<<512, 256>>>(n);
    bnfin2_kernel<<<1, C_B>>>(g3, b3, inv_n);

    gemm2_kernel<<<nblk64, 256>>>(w2);
    stats3_kernel<<<512, 256>>>(n);
    bnfin3_kernel<<<1, C_IN>>>(g2, b2, inv_n);

    final_kernel<<<(int)((tot_c / 4 + 255) / 256), 256>>>(data, out, tot_c);
}

// round 9
// speedup vs baseline: 1.0073x; 1.0073x over previous
#include <cuda_runtime.h>
#include <cuda_bf16.h>
#include <math.h>
#include <stdint.h>

#define C_IN   256
#define C_B    64
#define K_TAP  27
#define N_MAX  200000
#define BN_EPS 1e-3f

// ---------------- scratch (device globals; no allocation) ----------------
__device__ float g_h1[(size_t)N_MAX * C_B];   // conv1x1a raw
__device__ float g_h2[(size_t)N_MAX * C_B];   // octree conv raw
__device__ float g_h3[(size_t)N_MAX * C_IN];  // conv1x1b raw

__device__ __nv_bfloat16 g_h1h[(size_t)N_MAX * C_B];  // act1 hi
__device__ __nv_bfloat16 g_h1l[(size_t)N_MAX * C_B];  // act1 lo
__device__ __nv_bfloat16 g_w3h[K_TAP * C_B * C_B];    // w3 [k][c][d] hi
__device__ __nv_bfloat16 g_w3l[K_TAP * C_B * C_B];    // lo

__device__ float g_sum1[C_B],  g_sq1[C_B],  g_a1[C_B],  g_c1[C_B];
__device__ float g_sum2[C_B],  g_sq2[C_B],  g_a2[C_B],  g_c2[C_B];
__device__ float g_sum3[C_IN], g_sq3[C_IN], g_a3[C_IN], g_c3[C_IN];

__device__ __forceinline__ float gelu_exact(float x) {
    return 0.5f * x * (1.0f + erff(x * 0.70710678118654752440f));
}

// ---------------- stats reset ----------------
__global__ void zero_stats_kernel() {
    int t = threadIdx.x;
    if (t < C_B)  { g_sum1[t] = 0.f; g_sq1[t] = 0.f; g_sum2[t] = 0.f; g_sq2[t] = 0.f; }
    if (t < C_IN) { g_sum3[t] = 0.f; g_sq3[t] = 0.f; }
}

// ---------------- GEMM1: h1 = data[N,256] @ w1[256,64] (fp32) ----------------
__global__ void gemm1_kernel(const float* __restrict__ data,
                             const float* __restrict__ w1) {
    __shared__ float sA[64][36];
    __shared__ float sB[32][64];
    const int tid = threadIdx.x;
    const int tx = tid & 15, ty = tid >> 4;
    const int row0 = blockIdx.x * 64;

    const int lr = tid >> 2;
    const int lk = (tid & 3) * 8;
    const int br = tid >> 3;
    const int bc = (tid & 7) * 8;

    float acc[4][4] = {};

    for (int kb = 0; kb < C_IN; kb += 32) {
        const float4* ap = (const float4*)(data + (size_t)(row0 + lr) * C_IN + kb + lk);
        float4 a0 = ap[0], a1 = ap[1];
        *(float4*)&sA[lr][lk]     = a0;
        *(float4*)&sA[lr][lk + 4] = a1;

        const float4* bp = (const float4*)(w1 + (size_t)(kb + br) * C_B + bc);
        float4 b0 = bp[0], b1 = bp[1];
        *(float4*)&sB[br][bc]     = b0;
        *(float4*)&sB[br][bc + 4] = b1;
        __syncthreads();

        #pragma unroll
        for (int kk = 0; kk < 32; kk += 4) {
            float4 av[4];
            #pragma unroll
            for (int i = 0; i < 4; i++) av[i] = *(const float4*)&sA[ty * 4 + i][kk];
            #pragma unroll
            for (int u = 0; u < 4; u++) {
                float4 w = *(const float4*)&sB[kk + u][tx * 4];
                #pragma unroll
                for (int i = 0; i < 4; i++) {
                    float a = (&av[i].x)[u];
                    acc[i][0] = fmaf(a, w.x, acc[i][0]);
                    acc[i][1] = fmaf(a, w.y, acc[i][1]);
                    acc[i][2] = fmaf(a, w.z, acc[i][2]);
                    acc[i][3] = fmaf(a, w.w, acc[i][3]);
                }
            }
        }
        __syncthreads();
    }

    #pragma unroll
    for (int i = 0; i < 4; i++) {
        *(float4*)&g_h1[(size_t)(row0 + ty * 4 + i) * C_B + tx * 4] =
            make_float4(acc[i][0], acc[i][1], acc[i][2], acc[i][3]);
    }
}

// ---------------- per-channel stats ----------------
template<int CC>
__device__ __forceinline__ void stats_body(const float* __restrict__ x, int n,
                                           float* __restrict__ sums,
                                           float* __restrict__ sqs) {
    __shared__ float sm[256], qm[256];
    const int tid = threadIdx.x;
    const int col = tid % CC;
    const int rid = tid / CC;
    const int rpt = 256 / CC;

    long long rows_per_blk = (n + gridDim.x - 1) / gridDim.x;
    long long r0 = (long long)blockIdx.x * rows_per_blk;
    long long r1 = r0 + rows_per_blk; if (r1 > n) r1 = n;

    float s = 0.f, q = 0.f;
    for (long long r = r0 + rid; r < r1; r += rpt) {
        float v = x[r * CC + col];
        s += v; q += v * v;
    }
    sm[tid] = s; qm[tid] = q;
    __syncthreads();
    for (int off = 128; off >= CC; off >>= 1) {
        if (tid < off) { sm[tid] += sm[tid + off]; qm[tid] += qm[tid + off]; }
        __syncthreads();
    }
    if (tid < CC) {
        atomicAdd(&sums[tid], sm[tid]);
        atomicAdd(&sqs[tid],  qm[tid]);
    }
}

__global__ void stats1_kernel(int n) { stats_body<C_B >(g_h1, n, g_sum1, g_sq1); }
__global__ void stats2_kernel(int n) { stats_body<C_B >(g_h2, n, g_sum2, g_sq2); }
__global__ void stats3_kernel(int n) { stats_body<C_IN>(g_h3, n, g_sum3, g_sq3); }

// ---------------- BN finalize ----------------
__device__ __forceinline__ void bnfin_body(const float* sums, const float* sqs,
                                           const float* __restrict__ g,
                                           const float* __restrict__ b,
                                           float* a, float* c, float inv_n) {
    int t = threadIdx.x;
    float m = sums[t] * inv_n;
    float v = sqs[t] * inv_n - m * m;
    if (v < 0.f) v = 0.f;
    float s = g[t] * rsqrtf(v + BN_EPS);
    a[t] = s;
    c[t] = b[t] - m * s;
}
__global__ void bnfin1_kernel(const float* __restrict__ g, const float* __restrict__ b, float inv_n)
{ bnfin_body(g_sum1, g_sq1, g, b, g_a1, g_c1, inv_n); }
__global__ void bnfin2_kernel(const float* __restrict__ g, const float* __restrict__ b, float inv_n)
{ bnfin_body(g_sum2, g_sq2, g, b, g_a2, g_c2, inv_n); }
__global__ void bnfin3_kernel(const float* __restrict__ g, const float* __restrict__ b, float inv_n)
{ bnfin_body(g_sum3, g_sq3, g, b, g_a3, g_c3, inv_n); }

// ---------------- act1: BN+GELU, write bf16 hi/lo split ----------------
__global__ void act1_split_kernel(long long total) {
    long long i = ((long long)blockIdx.x * blockDim.x + threadIdx.x) * 4;
    if (i >= total) return;
    float4 v = *(const float4*)&g_h1[i];
    int c = (int)(i & (C_B - 1));
    float x0 = gelu_exact(fmaf(g_a1[c],     v.x, g_c1[c]));
    float x1 = gelu_exact(fmaf(g_a1[c + 1], v.y, g_c1[c + 1]));
    float x2 = gelu_exact(fmaf(g_a1[c + 2], v.z, g_c1[c + 2]));
    float x3 = gelu_exact(fmaf(g_a1[c + 3], v.w, g_c1[c + 3]));

    __nv_bfloat16 h0 = __float2bfloat16(x0), h1 = __float2bfloat16(x1);
    __nv_bfloat16 h2 = __float2bfloat16(x2), h3 = __float2bfloat16(x3);
    __nv_bfloat16 l0 = __float2bfloat16(x0 - __bfloat162float(h0));
    __nv_bfloat16 l1 = __float2bfloat16(x1 - __bfloat162float(h1));
    __nv_bfloat16 l2 = __float2bfloat16(x2 - __bfloat162float(h2));
    __nv_bfloat16 l3 = __float2bfloat16(x3 - __bfloat162float(h3));

    ushort4 ph = make_ushort4(*(unsigned short*)&h0, *(unsigned short*)&h1,
                              *(unsigned short*)&h2, *(unsigned short*)&h3);
    ushort4 pl = make_ushort4(*(unsigned short*)&l0, *(unsigned short*)&l1,
                              *(unsigned short*)&l2, *(unsigned short*)&l3);
    *(ushort4*)((unsigned short*)g_h1h + i) = ph;
    *(ushort4*)((unsigned short*)g_h1l + i) = pl;
}

// ---------------- w3 split (keep [k][c][d] layout) ----------------
__global__ void w3_split_kernel(const float* __restrict__ w3) {
    int i = blockIdx.x * blockDim.x + threadIdx.x;
    if (i >= K_TAP * C_B * C_B) return;
    float v = w3[i];
    __nv_bfloat16 h = __float2bfloat16(v);
    __nv_bfloat16 l = __float2bfloat16(v - __bfloat162float(h));
    g_w3h[i] = h;
    g_w3l[i] = l;
}

// ============== octree conv via mma.sync (HMMA bf16, hi/lo split) ==============
// h2[128,64] per CTA; A = gathered act1 rows (bf16 hi/lo), B = w3[k] as [c][d].
// Warp tile 32x32 (2 M-tiles x 4 N-tiles). 3 split terms: AhWh + AhWl + AlWh.

#define SROW 72           // smem row stride in bf16 elems (144 B) - bank-conflict free
#define OFF_IDX 0                                  // 27*128 ints = 13824 B
#define OFF_AH  13824                              // 128*144 = 18432 B
#define OFF_AL  (OFF_AH + 128 * 144)               // 18432 B
#define OFF_WH  (OFF_AL + 128 * 144)               // 64*144 = 9216 B
#define OFF_WL  (OFF_WH + 64 * 144)                // 9216 B
#define OCT_SMEM (OFF_WL + 64 * 144)               // 69120 B

__device__ __forceinline__ uint32_t smem_u32(const void* p) {
    uint32_t a;
    asm("{ .reg .u64 t; cvta.to.shared.u64 t, %1; cvt.u32.u64 %0, t; }"
        : "=r"(a) : "l"(p));
    return a;
}
__device__ __forceinline__ void ldsm_x4(uint32_t* r, uint32_t addr) {
    asm volatile("ldmatrix.sync.aligned.m8n8.x4.shared.b16 {%0,%1,%2,%3}, [%4];"
                 : "=r"(r[0]), "=r"(r[1]), "=r"(r[2]), "=r"(r[3]) : "r"(addr));
}
__device__ __forceinline__ void ldsm_x4_t(uint32_t* r, uint32_t addr) {
    asm volatile("ldmatrix.sync.aligned.m8n8.x4.trans.shared.b16 {%0,%1,%2,%3}, [%4];"
                 : "=r"(r[0]), "=r"(r[1]), "=r"(r[2]), "=r"(r[3]) : "r"(addr));
}
__device__ __forceinline__ void mma_bf16(float* d, const uint32_t* a, const uint32_t* b) {
    asm volatile(
        "mma.sync.aligned.m16n8k16.row.col.f32.bf16.bf16.f32 "
        "{%0,%1,%2,%3}, {%4,%5,%6,%7}, {%8,%9}, {%0,%1,%2,%3};"
        : "+f"(d[0]), "+f"(d[1]), "+f"(d[2]), "+f"(d[3])
        : "r"(a[0]), "r"(a[1]), "r"(a[2]), "r"(a[3]), "r"(b[0]), "r"(b[1]));
}

__global__ void __launch_bounds__(256) octconv_mma_kernel(const int* __restrict__ neigh,
                                                          int n) {
    extern __shared__ char smem[];
    const uint32_t sb = smem_u32(smem);
    const int tid = threadIdx.x;
    const int wid = tid >> 5, lane = tid & 31;
    const int wr = wid & 3, wc = wid >> 2;       // warp row band (32), col band (32)
    const int row0 = blockIdx.x * 128;

    int* sIdx = (int*)(smem + OFF_IDX);
    const uint4* h1h4 = (const uint4*)g_h1h;
    const uint4* h1l4 = (const uint4*)g_h1l;
    const uint4* w3h4 = (const uint4*)g_w3h;
    const uint4* w3l4 = (const uint4*)g_w3l;

    // stage gather indices: sIdx[k][r]
    for (int i = tid; i < K_TAP * 128; i += 256) {
        int r = i / K_TAP, k = i - r * K_TAP;
        int nr = row0 + r;
        sIdx[k * 128 + r] = (nr < n) ? neigh[(size_t)nr * K_TAP + k] : 0;
    }
    __syncthreads();

    // stage tap 0
    {
        const int* idx = sIdx;
        #pragma unroll
        for (int j = 0; j < 4; j++) {
            int cid = tid + 256 * j;              // 0..1023
            int r = cid >> 3, q = cid & 7;
            int gr = idx[r];
            *(uint4*)(smem + OFF_AH + r * 144 + q * 16) = h1h4[(size_t)gr * 8 + q];
            *(uint4*)(smem + OFF_AL + r * 144 + q * 16) = h1l4[(size_t)gr * 8 + q];
        }
        #pragma unroll
        for (int j = 0; j < 2; j++) {
            int cid = tid + 256 * j;              // 0..511
            int r = cid >> 3, q = cid & 7;
            *(uint4*)(smem + OFF_WH + r * 144 + q * 16) = w3h4[cid];
            *(uint4*)(smem + OFF_WL + r * 144 + q * 16) = w3l4[cid];
        }
    }
    __syncthreads();

    float acc[2][4][4];
    #pragma unroll
    for (int mt = 0; mt < 2; mt++)
        #pragma unroll
        for (int nt = 0; nt < 4; nt++)
            #pragma unroll
            for (int q = 0; q < 4; q++) acc[mt][nt][q] = 0.f;

    // per-lane ldmatrix address components
    const uint32_t aOff = (uint32_t)((wr * 32 + (lane & 15)) * 144 + (lane >> 4) * 16);
    const uint32_t bOff = (uint32_t)((lane & 15) * 144 + (wc * 32 + (lane >> 4) * 8) * 2);

    for (int k = 0; k < K_TAP; k++) {
        // prefetch tap k+1 gather into registers
        uint4 pAh[4], pAl[4], pWh[2], pWl[2];
        if (k + 1 < K_TAP) {
            const int* idx = sIdx + (k + 1) * 128;
            #pragma unroll
            for (int j = 0; j < 4; j++) {
                int cid = tid + 256 * j;
                int r = cid >> 3, q = cid & 7;
                int gr = idx[r];
                pAh[j] = h1h4[(size_t)gr * 8 + q];
                pAl[j] = h1l4[(size_t)gr * 8 + q];
            }
            #pragma unroll
            for (int j = 0; j < 2; j++) {
                int cid = tid + 256 * j;
                pWh[j] = w3h4[(size_t)(k + 1) * 512 + cid];
                pWl[j] = w3l4[(size_t)(k + 1) * 512 + cid];
            }
        }

        // compute on current buffer
        #pragma unroll
        for (int ks = 0; ks < 4; ks++) {
            uint32_t ah[2][4], al[2][4], bh[2][4], bl[2][4];
            #pragma unroll
            for (int mt = 0; mt < 2; mt++) {
                uint32_t ad = sb + OFF_AH + aOff + (uint32_t)(mt * 16 * 144 + ks * 32);
                ldsm_x4(ah[mt], ad);
                ldsm_x4(al[mt], ad + (OFF_AL - OFF_AH));
            }
            #pragma unroll
            for (int nt2 = 0; nt2 < 2; nt2++) {
                uint32_t bd = sb + OFF_WH + bOff + (uint32_t)(ks * 16 * 144 + nt2 * 32);
                ldsm_x4_t(bh[nt2], bd);
                ldsm_x4_t(bl[nt2], bd + (OFF_WL - OFF_WH));
            }
            #pragma unroll
            for (int mt = 0; mt < 2; mt++) {
                #pragma unroll
                for (int nt = 0; nt < 4; nt++) {
                    const uint32_t* ph = &bh[nt >> 1][(nt & 1) * 2];
                    const uint32_t* pl = &bl[nt >> 1][(nt & 1) * 2];
                    mma_bf16(acc[mt][nt], ah[mt], ph);
                    mma_bf16(acc[mt][nt], ah[mt], pl);
                    mma_bf16(acc[mt][nt], al[mt], ph);
                }
            }
        }
        __syncthreads();

        // store prefetched tap k+1
        if (k + 1 < K_TAP) {
            #pragma unroll
            for (int j = 0; j < 4; j++) {
                int cid = tid + 256 * j;
                int r = cid >> 3, q = cid & 7;
                *(uint4*)(smem + OFF_AH + r * 144 + q * 16) = pAh[j];
                *(uint4*)(smem + OFF_AL + r * 144 + q * 16) = pAl[j];
            }
            #pragma unroll
            for (int j = 0; j < 2; j++) {
                int cid = tid + 256 * j;
                int r = cid >> 3, q = cid & 7;
                *(uint4*)(smem + OFF_WH + r * 144 + q * 16) = pWh[j];
                *(uint4*)(smem + OFF_WL + r * 144 + q * 16) = pWl[j];
            }
            __syncthreads();
        }
    }

    // epilogue: write acc to g_h2
    #pragma unroll
    for (int mt = 0; mt < 2; mt++) {
        int r0 = row0 + wr * 32 + mt * 16 + (lane >> 2);
        #pragma unroll
        for (int nt = 0; nt < 4; nt++) {
            int col = wc * 32 + nt * 8 + (lane & 3) * 2;
            if (r0 < n)
                *(float2*)&g_h2[(size_t)r0 * C_B + col] =
                    make_float2(acc[mt][nt][0], acc[mt][nt][1]);
            if (r0 + 8 < n)
                *(float2*)&g_h2[(size_t)(r0 + 8) * C_B + col] =
                    make_float2(acc[mt][nt][2], acc[mt][nt][3]);
        }
    }
}

// ---------------- GEMM2: h3 = act2(h2)[N,64] @ w2[64,256] (fp32, act fused) ----------------
__global__ void gemm2_kernel(const float* __restrict__ w2) {
    __shared__ float sA[64][36];
    __shared__ float sB[32][256];
    const int tid = threadIdx.x;
    const int tx = tid & 15, ty = tid >> 4;
    const int row0 = blockIdx.x * 64;

    float acc[4][16] = {};

    for (int cb = 0; cb < C_B; cb += 32) {
        {
            int lr = tid >> 2;
            int cofs = (tid & 3) * 8;
            const float* src = g_h2 + (size_t)(row0 + lr) * C_B + cb + cofs;
            float4 v0 = *(const float4*)(src);
            float4 v1 = *(const float4*)(src + 4);
            int c = cb + cofs;
            v0.x = gelu_exact(fmaf(g_a2[c],     v0.x, g_c2[c]));
            v0.y = gelu_exact(fmaf(g_a2[c + 1], v0.y, g_c2[c + 1]));
            v0.z = gelu_exact(fmaf(g_a2[c + 2], v0.z, g_c2[c + 2]));
            v0.w = gelu_exact(fmaf(g_a2[c + 3], v0.w, g_c2[c + 3]));
            v1.x = gelu_exact(fmaf(g_a2[c + 4], v1.x, g_c2[c + 4]));
            v1.y = gelu_exact(fmaf(g_a2[c + 5], v1.y, g_c2[c + 5]));
            v1.z = gelu_exact(fmaf(g_a2[c + 6], v1.z, g_c2[c + 6]));
            v1.w = gelu_exact(fmaf(g_a2[c + 7], v1.w, g_c2[c + 7]));
            *(float4*)&sA[lr][cofs]     = v0;
            *(float4*)&sA[lr][cofs + 4] = v1;
        }
        {
            const float4* wp = (const float4*)(w2 + (size_t)cb * C_IN);
            #pragma unroll
            for (int j = 0; j < 8; j++)
                ((float4*)sB)[tid + 256 * j] = wp[tid + 256 * j];
        }
        __syncthreads();

        #pragma unroll
        for (int c = 0; c < 32; c += 4) {
            float4 av[4];
            #pragma unroll
            for (int i = 0; i < 4; i++) av[i] = *(const float4*)&sA[ty * 4 + i][c];
            #pragma unroll
            for (int u = 0; u < 4; u++) {
                #pragma unroll
                for (int j4 = 0; j4 < 4; j4++) {
                    float4 w = *(const float4*)&sB[c + u][tx * 4 + j4 * 64];
                    #pragma unroll
                    for (int i = 0; i < 4; i++) {
                        float a = (&av[i].x)[u];
                        acc[i][j4 * 4 + 0] = fmaf(a, w.x, acc[i][j4 * 4 + 0]);
                        acc[i][j4 * 4 + 1] = fmaf(a, w.y, acc[i][j4 * 4 + 1]);
                        acc[i][j4 * 4 + 2] = fmaf(a, w.z, acc[i][j4 * 4 + 2]);
                        acc[i][j4 * 4 + 3] = fmaf(a, w.w, acc[i][j4 * 4 + 3]);
                    }
                }
            }
        }
        __syncthreads();
    }

    #pragma unroll
    for (int i = 0; i < 4; i++) {
        #pragma unroll
        for (int j4 = 0; j4 < 4; j4++) {
            *(float4*)&g_h3[(size_t)(row0 + ty * 4 + i) * C_IN + tx * 4 + j4 * 64] =
                make_float4(acc[i][j4 * 4 + 0], acc[i][j4 * 4 + 1],
                            acc[i][j4 * 4 + 2], acc[i][j4 * 4 + 3]);
        }
    }
}

// ---------------- epilogue: out = elu(bn3(h3) + data) ----------------
__global__ void final_kernel(const float* __restrict__ data,
                             float* __restrict__ out, long long total) {
    long long i = ((long long)blockIdx.x * blockDim.x + threadIdx.x) * 4;
    if (i >= total) return;
    float4 h = *(const float4*)&g_h3[i];
    float4 d = *(const float4*)&data[i];
    int c = (int)(i & (C_IN - 1));
    float x;
    x = fmaf(g_a3[c],     h.x, g_c3[c]) + d.x; h.x = x > 0.f ? x : expm1f(x);
    x = fmaf(g_a3[c + 1], h.y, g_c3[c + 1]) + d.y; h.y = x > 0.f ? x : expm1f(x);
    x = fmaf(g_a3[c + 2], h.z, g_c3[c + 2]) + d.z; h.z = x > 0.f ? x : expm1f(x);
    x = fmaf(g_a3[c + 3], h.w, g_c3[c + 3]) + d.w; h.w = x > 0.f ? x : expm1f(x);
    *(float4*)&out[i] = h;
}

// ---------------- launch ----------------
extern "C" void kernel_launch(void* const* d_in, const int* in_sizes, int n_in,
                              void* d_out, int out_size) {
    const float* data  = (const float*)d_in[0];
    const int*   neigh = (const int*)d_in[1];
    const float* w1 = (const float*)d_in[2];
    const float* g1 = (const float*)d_in[3];
    const float* b1 = (const float*)d_in[4];
    const float* w3 = (const float*)d_in[5];
    const float* g3 = (const float*)d_in[6];
    const float* b3 = (const float*)d_in[7];
    const float* w2 = (const float*)d_in[8];
    const float* g2 = (const float*)d_in[9];
    const float* b2 = (const float*)d_in[10];
    float* out = (float*)d_out;

    const int n = in_sizes[0] / C_IN;
    const float inv_n = 1.0f / (float)n;
    const int nblk64 = n / 64;
    const int nblk128 = (n + 127) / 128;
    const long long tot_b = (long long)n * C_B;
    const long long tot_c = (long long)n * C_IN;

    cudaFuncSetAttribute(octconv_mma_kernel,
                         cudaFuncAttributeMaxDynamicSharedMemorySize, OCT_SMEM);

    zero_stats_kernel<<<1, 256>>>();
    w3_split_kernel<<<(K_TAP * C_B * C_B + 255) / 256, 256>>>(w3);

    gemm1_kernel<<<nblk64, 256>>>(data, w1);
    stats1_kernel<<<512, 256>>>(n);
    bnfin1_kernel<<<1, C_B>>>(g1, b1, inv_n);
    act1_split_kernel<<<(int)((tot_b / 4 + 255) / 256), 256>>>(tot_b);

    octconv_mma_kernel<<<nblk128, 256, OCT_SMEM>>>(neigh, n);
    stats2_kernel<<<512, 256>>>(n);
    bnfin2_kernel<<<1, C_B>>>(g3, b3, inv_n);

    gemm2_kernel<<<nblk64, 256>>>(w2);
    stats3_kernel<<<512, 256>>>(n);
    bnfin3_kernel<<<1, C_IN>>>(g2, b2, inv_n);

    final_kernel<<<(int)((tot_c / 4 + 255) / 256), 256>>>(data, out, tot_c);
}

// round 10
// speedup vs baseline: 1.1826x; 1.1740x over previous
#include <cuda_runtime.h>
#include <cuda_bf16.h>
#include <math.h>
#include <stdint.h>

#define C_IN   256
#define C_B    64
#define K_TAP  27
#define N_MAX  200000
#define BN_EPS 1e-3f

// ---------------- scratch (device globals; no allocation) ----------------
__device__ float g_h1[(size_t)N_MAX * C_B];   // conv1x1a raw
__device__ float g_h2[(size_t)N_MAX * C_B];   // octree conv raw
__device__ float g_h3[(size_t)N_MAX * C_IN];  // conv1x1b raw

__device__ __nv_bfloat16 g_h1h[(size_t)N_MAX * C_B];  // act1 hi
__device__ __nv_bfloat16 g_h1l[(size_t)N_MAX * C_B];  // act1 lo
__device__ __nv_bfloat16 g_w3h[K_TAP * C_B * C_B];    // w3 [k][c][d] hi
__device__ __nv_bfloat16 g_w3l[K_TAP * C_B * C_B];    // lo

__device__ float g_sum1[C_B],  g_sq1[C_B],  g_a1[C_B],  g_c1[C_B];
__device__ float g_sum2[C_B],  g_sq2[C_B],  g_a2[C_B],  g_c2[C_B];
__device__ float g_sum3[C_IN], g_sq3[C_IN], g_a3[C_IN], g_c3[C_IN];

__device__ __forceinline__ float gelu_exact(float x) {
    return 0.5f * x * (1.0f + erff(x * 0.70710678118654752440f));
}

// ---------------- mma/ldsm/cp.async helpers ----------------
__device__ __forceinline__ uint32_t smem_u32(const void* p) {
    uint32_t a;
    asm("{ .reg .u64 t; cvta.to.shared.u64 t, %1; cvt.u32.u64 %0, t; }"
        : "=r"(a) : "l"(p));
    return a;
}
__device__ __forceinline__ void ldsm_x4(uint32_t* r, uint32_t addr) {
    asm volatile("ldmatrix.sync.aligned.m8n8.x4.shared.b16 {%0,%1,%2,%3}, [%4];"
                 : "=r"(r[0]), "=r"(r[1]), "=r"(r[2]), "=r"(r[3]) : "r"(addr));
}
__device__ __forceinline__ void ldsm_x4_t(uint32_t* r, uint32_t addr) {
    asm volatile("ldmatrix.sync.aligned.m8n8.x4.trans.shared.b16 {%0,%1,%2,%3}, [%4];"
                 : "=r"(r[0]), "=r"(r[1]), "=r"(r[2]), "=r"(r[3]) : "r"(addr));
}
__device__ __forceinline__ void mma_bf16(float* d, const uint32_t* a, const uint32_t* b) {
    asm volatile(
        "mma.sync.aligned.m16n8k16.row.col.f32.bf16.bf16.f32 "
        "{%0,%1,%2,%3}, {%4,%5,%6,%7}, {%8,%9}, {%0,%1,%2,%3};"
        : "+f"(d[0]), "+f"(d[1]), "+f"(d[2]), "+f"(d[3])
        : "r"(a[0]), "r"(a[1]), "r"(a[2]), "r"(a[3]), "r"(b[0]), "r"(b[1]));
}
__device__ __forceinline__ void cp16(uint32_t dst, const void* src) {
    asm volatile("cp.async.cg.shared.global [%0], [%1], 16;" :: "r"(dst), "l"(src));
}
__device__ __forceinline__ void cp_commit() {
    asm volatile("cp.async.commit_group;" ::: "memory");
}

__device__ __forceinline__ uint32_t bf2pack(__nv_bfloat16 a, __nv_bfloat16 b) {
    unsigned short ua = *(unsigned short*)&a, ub = *(unsigned short*)&b;
    return (uint32_t)ua | ((uint32_t)ub << 16);
}
__device__ __forceinline__ void split4(float4 v, uint2* hi, uint2* lo) {
    __nv_bfloat16 h0 = __float2bfloat16(v.x), h1 = __float2bfloat16(v.y);
    __nv_bfloat16 h2 = __float2bfloat16(v.z), h3 = __float2bfloat16(v.w);
    __nv_bfloat16 l0 = __float2bfloat16(v.x - __bfloat162float(h0));
    __nv_bfloat16 l1 = __float2bfloat16(v.y - __bfloat162float(h1));
    __nv_bfloat16 l2 = __float2bfloat16(v.z - __bfloat162float(h2));
    __nv_bfloat16 l3 = __float2bfloat16(v.w - __bfloat162float(h3));
    hi->x = bf2pack(h0, h1); hi->y = bf2pack(h2, h3);
    lo->x = bf2pack(l0, l1); lo->y = bf2pack(l2, l3);
}

// ---------------- stats reset ----------------
__global__ void zero_stats_kernel() {
    int t = threadIdx.x;
    if (t < C_B)  { g_sum1[t] = 0.f; g_sq1[t] = 0.f; g_sum2[t] = 0.f; g_sq2[t] = 0.f; }
    if (t < C_IN) { g_sum3[t] = 0.f; g_sq3[t] = 0.f; }
}

// ---------------- per-channel stats ----------------
template<int CC>
__device__ __forceinline__ void stats_body(const float* __restrict__ x, int n,
                                           float* __restrict__ sums,
                                           float* __restrict__ sqs) {
    __shared__ float sm[256], qm[256];
    const int tid = threadIdx.x;
    const int col = tid % CC;
    const int rid = tid / CC;
    const int rpt = 256 / CC;

    long long rows_per_blk = (n + gridDim.x - 1) / gridDim.x;
    long long r0 = (long long)blockIdx.x * rows_per_blk;
    long long r1 = r0 + rows_per_blk; if (r1 > n) r1 = n;

    float s = 0.f, q = 0.f;
    for (long long r = r0 + rid; r < r1; r += rpt) {
        float v = x[r * CC + col];
        s += v; q += v * v;
    }
    sm[tid] = s; qm[tid] = q;
    __syncthreads();
    for (int off = 128; off >= CC; off >>= 1) {
        if (tid < off) { sm[tid] += sm[tid + off]; qm[tid] += qm[tid + off]; }
        __syncthreads();
    }
    if (tid < CC) {
        atomicAdd(&sums[tid], sm[tid]);
        atomicAdd(&sqs[tid],  qm[tid]);
    }
}

__global__ void stats1_kernel(int n) { stats_body<C_B >(g_h1, n, g_sum1, g_sq1); }
__global__ void stats2_kernel(int n) { stats_body<C_B >(g_h2, n, g_sum2, g_sq2); }
__global__ void stats3_kernel(int n) { stats_body<C_IN>(g_h3, n, g_sum3, g_sq3); }

// ---------------- BN finalize ----------------
__device__ __forceinline__ void bnfin_body(const float* sums, const float* sqs,
                                           const float* __restrict__ g,
                                           const float* __restrict__ b,
                                           float* a, float* c, float inv_n) {
    int t = threadIdx.x;
    float m = sums[t] * inv_n;
    float v = sqs[t] * inv_n - m * m;
    if (v < 0.f) v = 0.f;
    float s = g[t] * rsqrtf(v + BN_EPS);
    a[t] = s;
    c[t] = b[t] - m * s;
}
__global__ void bnfin1_kernel(const float* __restrict__ g, const float* __restrict__ b, float inv_n)
{ bnfin_body(g_sum1, g_sq1, g, b, g_a1, g_c1, inv_n); }
__global__ void bnfin2_kernel(const float* __restrict__ g, const float* __restrict__ b, float inv_n)
{ bnfin_body(g_sum2, g_sq2, g, b, g_a2, g_c2, inv_n); }
__global__ void bnfin3_kernel(const float* __restrict__ g, const float* __restrict__ b, float inv_n)
{ bnfin_body(g_sum3, g_sq3, g, b, g_a3, g_c3, inv_n); }

// ---------------- act1: BN+GELU, write bf16 hi/lo split ----------------
__global__ void act1_split_kernel(long long total) {
    long long i = ((long long)blockIdx.x * blockDim.x + threadIdx.x) * 4;
    if (i >= total) return;
    float4 v = *(const float4*)&g_h1[i];
    int c = (int)(i & (C_B - 1));
    v.x = gelu_exact(fmaf(g_a1[c],     v.x, g_c1[c]));
    v.y = gelu_exact(fmaf(g_a1[c + 1], v.y, g_c1[c + 1]));
    v.z = gelu_exact(fmaf(g_a1[c + 2], v.z, g_c1[c + 2]));
    v.w = gelu_exact(fmaf(g_a1[c + 3], v.w, g_c1[c + 3]));
    uint2 hi, lo; split4(v, &hi, &lo);
    *(uint2*)((unsigned short*)g_h1h + i) = hi;
    *(uint2*)((unsigned short*)g_h1l + i) = lo;
}

// ---------------- w3 split (keep [k][c][d] layout) ----------------
__global__ void w3_split_kernel(const float* __restrict__ w3) {
    int i = blockIdx.x * blockDim.x + threadIdx.x;
    if (i >= K_TAP * C_B * C_B) return;
    float v = w3[i];
    __nv_bfloat16 h = __float2bfloat16(v);
    __nv_bfloat16 l = __float2bfloat16(v - __bfloat162float(h));
    g_w3h[i] = h;
    g_w3l[i] = l;
}

// ============== GEMM1 via mma.sync: h1 = data[N,256] @ w1[256,64] ==============
// CTA 128x64, 8 warps (wr band 32 rows, wc band 32 cols), K chunks of 64.
#define G1_AH 0
#define G1_AL 18432
#define G1_BH 36864
#define G1_BL 46080
#define G1_SMEM 55296

__global__ void __launch_bounds__(256) gemm1_mma_kernel(const float* __restrict__ data,
                                                        const float* __restrict__ w1, int n) {
    extern __shared__ char smem[];
    const uint32_t sb = smem_u32(smem);
    const int tid = threadIdx.x;
    const int wid = tid >> 5, lane = tid & 31;
    const int wr = wid & 3, wc = wid >> 2;
    const int row0 = blockIdx.x * 128;

    float acc[2][4][4] = {};
    const uint32_t aOff = (uint32_t)((wr * 32 + (lane & 15)) * 144 + (lane >> 4) * 16);
    const uint32_t bOff = (uint32_t)((lane & 15) * 144 + (wc * 32 + (lane >> 4) * 8) * 2);

    for (int kb = 0; kb < C_IN; kb += 64) {
        #pragma unroll
        for (int j = 0; j < 8; j++) {
            int s = tid + 256 * j;
            int r = s >> 4, f4 = s & 15;
            int rr = row0 + r; if (rr >= n) rr = n - 1;
            float4 v = *(const float4*)(data + (size_t)rr * C_IN + kb + f4 * 4);
            uint2 hi, lo; split4(v, &hi, &lo);
            *(uint2*)(smem + G1_AH + r * 144 + f4 * 8) = hi;
            *(uint2*)(smem + G1_AL + r * 144 + f4 * 8) = lo;
        }
        #pragma unroll
        for (int j = 0; j < 4; j++) {
            int s = tid + 256 * j;
            int r = s >> 4, f4 = s & 15;
            float4 v = *(const float4*)(w1 + (size_t)(kb + r) * C_B + f4 * 4);
            uint2 hi, lo; split4(v, &hi, &lo);
            *(uint2*)(smem + G1_BH + r * 144 + f4 * 8) = hi;
            *(uint2*)(smem + G1_BL + r * 144 + f4 * 8) = lo;
        }
        __syncthreads();

        #pragma unroll
        for (int ks = 0; ks < 4; ks++) {
            uint32_t ah[2][4], al[2][4], bh[2][4], bl[2][4];
            #pragma unroll
            for (int mt = 0; mt < 2; mt++) {
                uint32_t ad = sb + G1_AH + aOff + (uint32_t)(mt * 16 * 144 + ks * 32);
                ldsm_x4(ah[mt], ad);
                ldsm_x4(al[mt], ad + (G1_AL - G1_AH));
            }
            #pragma unroll
            for (int nt2 = 0; nt2 < 2; nt2++) {
                uint32_t bd = sb + G1_BH + bOff + (uint32_t)(ks * 16 * 144 + nt2 * 32);
                ldsm_x4_t(bh[nt2], bd);
                ldsm_x4_t(bl[nt2], bd + (G1_BL - G1_BH));
            }
            #pragma unroll
            for (int mt = 0; mt < 2; mt++) {
                #pragma unroll
                for (int nt = 0; nt < 4; nt++) {
                    const uint32_t* ph = &bh[nt >> 1][(nt & 1) * 2];
                    const uint32_t* pl = &bl[nt >> 1][(nt & 1) * 2];
                    mma_bf16(acc[mt][nt], ah[mt], ph);
                    mma_bf16(acc[mt][nt], ah[mt], pl);
                    mma_bf16(acc[mt][nt], al[mt], ph);
                }
            }
        }
        __syncthreads();
    }

    #pragma unroll
    for (int mt = 0; mt < 2; mt++) {
        int r0 = row0 + wr * 32 + mt * 16 + (lane >> 2);
        #pragma unroll
        for (int nt = 0; nt < 4; nt++) {
            int col = wc * 32 + nt * 8 + (lane & 3) * 2;
            if (r0 < n)
                *(float2*)&g_h1[(size_t)r0 * C_B + col] =
                    make_float2(acc[mt][nt][0], acc[mt][nt][1]);
            if (r0 + 8 < n)
                *(float2*)&g_h1[(size_t)(r0 + 8) * C_B + col] =
                    make_float2(acc[mt][nt][2], acc[mt][nt][3]);
        }
    }
}

// ============== octree conv via mma.sync + cp.async double buffering ==============
#define OB_AH 0
#define OB_AL 18432
#define OB_WH 36864
#define OB_WL 46080
#define OB_SZ 55296
#define OFF_IDX 0
#define OFF_BUF 13824
#define OCT_SMEM (OFF_BUF + 2 * OB_SZ)   // 124416

__device__ __forceinline__ void issue_tap(uint32_t sb, int buf, int k,
                                          const int* sIdx, int tid) {
    const uint32_t base = sb + OFF_BUF + buf * OB_SZ;
    const int* idx = sIdx + (k << 7);
    #pragma unroll
    for (int j = 0; j < 4; j++) {
        int cid = tid + 256 * j;              // 0..1023
        int r = cid >> 3, q = cid & 7;
        int gr = idx[r];
        uint32_t d = base + (uint32_t)(r * 144 + q * 16);
        cp16(d + OB_AH, g_h1h + (size_t)gr * C_B + q * 8);
        cp16(d + OB_AL, g_h1l + (size_t)gr * C_B + q * 8);
    }
    #pragma unroll
    for (int j = 0; j < 2; j++) {
        int cid = tid + 256 * j;              // 0..511
        int r = cid >> 3, q = cid & 7;
        uint32_t d = base + (uint32_t)(r * 144 + q * 16);
        cp16(d + OB_WH, g_w3h + (size_t)k * 4096 + cid * 8);
        cp16(d + OB_WL, g_w3l + (size_t)k * 4096 + cid * 8);
    }
}

__global__ void __launch_bounds__(256) octconv_mma_kernel(const int* __restrict__ neigh,
                                                          int n) {
    extern __shared__ char smem[];
    const uint32_t sb = smem_u32(smem);
    const int tid = threadIdx.x;
    const int wid = tid >> 5, lane = tid & 31;
    const int wr = wid & 3, wc = wid >> 2;
    const int row0 = blockIdx.x * 128;

    int* sIdx = (int*)(smem + OFF_IDX);
    for (int i = tid; i < K_TAP * 128; i += 256) {
        int r = i / K_TAP, k = i - r * K_TAP;
        int nr = row0 + r;
        sIdx[k * 128 + r] = (nr < n) ? neigh[(size_t)nr * K_TAP + k] : 0;
    }
    __syncthreads();

    issue_tap(sb, 0, 0, sIdx, tid);
    cp_commit();

    float acc[2][4][4] = {};
    const uint32_t aOff = (uint32_t)((wr * 32 + (lane & 15)) * 144 + (lane >> 4) * 16);
    const uint32_t bOff = (uint32_t)((lane & 15) * 144 + (wc * 32 + (lane >> 4) * 8) * 2);

    for (int k = 0; k < K_TAP; k++) {
        const int b = k & 1;
        if (k + 1 < K_TAP) {
            issue_tap(sb, b ^ 1, k + 1, sIdx, tid);
            cp_commit();
            asm volatile("cp.async.wait_group 1;" ::: "memory");
        } else {
            asm volatile("cp.async.wait_group 0;" ::: "memory");
        }
        __syncthreads();

        const uint32_t base = sb + OFF_BUF + b * OB_SZ;
        #pragma unroll
        for (int ks = 0; ks < 4; ks++) {
            uint32_t ah[2][4], al[2][4], bh[2][4], bl[2][4];
            #pragma unroll
            for (int mt = 0; mt < 2; mt++) {
                uint32_t ad = base + OB_AH + aOff + (uint32_t)(mt * 16 * 144 + ks * 32);
                ldsm_x4(ah[mt], ad);
                ldsm_x4(al[mt], ad + (OB_AL - OB_AH));
            }
            #pragma unroll
            for (int nt2 = 0; nt2 < 2; nt2++) {
                uint32_t bd = base + OB_WH + bOff + (uint32_t)(ks * 16 * 144 + nt2 * 32);
                ldsm_x4_t(bh[nt2], bd);
                ldsm_x4_t(bl[nt2], bd + (OB_WL - OB_WH));
            }
            #pragma unroll
            for (int mt = 0; mt < 2; mt++) {
                #pragma unroll
                for (int nt = 0; nt < 4; nt++) {
                    const uint32_t* ph = &bh[nt >> 1][(nt & 1) * 2];
                    const uint32_t* pl = &bl[nt >> 1][(nt & 1) * 2];
                    mma_bf16(acc[mt][nt], ah[mt], ph);
                    mma_bf16(acc[mt][nt], ah[mt], pl);
                    mma_bf16(acc[mt][nt], al[mt], ph);
                }
            }
        }
        __syncthreads();
    }

    #pragma unroll
    for (int mt = 0; mt < 2; mt++) {
        int r0 = row0 + wr * 32 + mt * 16 + (lane >> 2);
        #pragma unroll
        for (int nt = 0; nt < 4; nt++) {
            int col = wc * 32 + nt * 8 + (lane & 3) * 2;
            if (r0 < n)
                *(float2*)&g_h2[(size_t)r0 * C_B + col] =
                    make_float2(acc[mt][nt][0], acc[mt][nt][1]);
            if (r0 + 8 < n)
                *(float2*)&g_h2[(size_t)(r0 + 8) * C_B + col] =
                    make_float2(acc[mt][nt][2], acc[mt][nt][3]);
        }
    }
}

// ============== GEMM2 via mma.sync: h3 = act2(h2)[N,64] @ w2[64,256] ==============
// grid (nblk128, 2): CTA 128 rows x 128 cols. BN2+GELU+split fused in A staging.
#define G2_AH 0
#define G2_AL 18432
#define G2_BH 36864
#define G2_BL (36864 + 17408)
#define G2_SMEM (36864 + 2 * 17408)   // 71680

__global__ void __launch_bounds__(256) gemm2_mma_kernel(const float* __restrict__ w2, int n) {
    extern __shared__ char smem[];
    const uint32_t sb = smem_u32(smem);
    const int tid = threadIdx.x;
    const int wid = tid >> 5, lane = tid & 31;
    const int wr = wid & 3, wc = wid >> 2;
    const int row0 = blockIdx.x * 128;
    const int col0 = blockIdx.y * 128;

    // stage A with BN2+GELU+split
    #pragma unroll
    for (int j = 0; j < 8; j++) {
        int s = tid + 256 * j;
        int r = s >> 4, f4 = s & 15;
        int rr = row0 + r; if (rr >= n) rr = n - 1;
        float4 v = *(const float4*)(g_h2 + (size_t)rr * C_B + f4 * 4);
        int c = f4 * 4;
        v.x = gelu_exact(fmaf(g_a2[c],     v.x, g_c2[c]));
        v.y = gelu_exact(fmaf(g_a2[c + 1], v.y, g_c2[c + 1]));
        v.z = gelu_exact(fmaf(g_a2[c + 2], v.z, g_c2[c + 2]));
        v.w = gelu_exact(fmaf(g_a2[c + 3], v.w, g_c2[c + 3]));
        uint2 hi, lo; split4(v, &hi, &lo);
        *(uint2*)(smem + G2_AH + r * 144 + f4 * 8) = hi;
        *(uint2*)(smem + G2_AL + r * 144 + f4 * 8) = lo;
    }
    // stage B: w2[0..63][col0..col0+127]   (row stride 272 B = odd multiple of 16)
    #pragma unroll
    for (int j = 0; j < 8; j++) {
        int s = tid + 256 * j;                // 0..2047
        int r = s >> 5, f4 = s & 31;
        float4 v = *(const float4*)(w2 + (size_t)r * C_IN + col0 + f4 * 4);
        uint2 hi, lo; split4(v, &hi, &lo);
        *(uint2*)(smem + G2_BH + r * 272 + f4 * 8) = hi;
        *(uint2*)(smem + G2_BL + r * 272 + f4 * 8) = lo;
    }
    __syncthreads();

    float acc[2][8][4] = {};
    const uint32_t aOff = (uint32_t)((wr * 32 + (lane & 15)) * 144 + (lane >> 4) * 16);
    const uint32_t bOff = (uint32_t)((lane & 15) * 272 + (wc * 64 + (lane >> 4) * 8) * 2);

    #pragma unroll
    for (int ks = 0; ks < 4; ks++) {
        uint32_t ah[2][4], al[2][4], bh[4][4], bl[4][4];
        #pragma unroll
        for (int mt = 0; mt < 2; mt++) {
            uint32_t ad = sb + G2_AH + aOff + (uint32_t)(mt * 16 * 144 + ks * 32);
            ldsm_x4(ah[mt], ad);
            ldsm_x4(al[mt], ad + (G2_AL - G2_AH));
        }
        #pragma unroll
        for (int nt2 = 0; nt2 < 4; nt2++) {
            uint32_t bd = sb + G2_BH + bOff + (uint32_t)(ks * 16 * 272 + nt2 * 32);
            ldsm_x4_t(bh[nt2], bd);
            ldsm_x4_t(bl[nt2], bd + (G2_BL - G2_BH));
        }
        #pragma unroll
        for (int mt = 0; mt < 2; mt++) {
            #pragma unroll
            for (int nt = 0; nt < 8; nt++) {
                const uint32_t* ph = &bh[nt >> 1][(nt & 1) * 2];
                const uint32_t* pl = &bl[nt >> 1][(nt & 1) * 2];
                mma_bf16(acc[mt][nt], ah[mt], ph);
                mma_bf16(acc[mt][nt], ah[mt], pl);
                mma_bf16(acc[mt][nt], al[mt], ph);
            }
        }
    }

    #pragma unroll
    for (int mt = 0; mt < 2; mt++) {
        int r0 = row0 + wr * 32 + mt * 16 + (lane >> 2);
        #pragma unroll
        for (int nt = 0; nt < 8; nt++) {
            int col = col0 + wc * 64 + nt * 8 + (lane & 3) * 2;
            if (r0 < n)
                *(float2*)&g_h3[(size_t)r0 * C_IN + col] =
                    make_float2(acc[mt][nt][0], acc[mt][nt][1]);
            if (r0 + 8 < n)
                *(float2*)&g_h3[(size_t)(r0 + 8) * C_IN + col] =
                    make_float2(acc[mt][nt][2], acc[mt][nt][3]);
        }
    }
}

// ---------------- epilogue: out = elu(bn3(h3) + data) ----------------
__global__ void final_kernel(const float* __restrict__ data,
                             float* __restrict__ out, long long total) {
    long long i = ((long long)blockIdx.x * blockDim.x + threadIdx.x) * 4;
    if (i >= total) return;
    float4 h = *(const float4*)&g_h3[i];
    float4 d = *(const float4*)&data[i];
    int c = (int)(i & (C_IN - 1));
    float x;
    x = fmaf(g_a3[c],     h.x, g_c3[c]) + d.x; h.x = x > 0.f ? x : expm1f(x);
    x = fmaf(g_a3[c + 1], h.y, g_c3[c + 1]) + d.y; h.y = x > 0.f ? x : expm1f(x);
    x = fmaf(g_a3[c + 2], h.z, g_c3[c + 2]) + d.z; h.z = x > 0.f ? x : expm1f(x);
    x = fmaf(g_a3[c + 3], h.w, g_c3[c + 3]) + d.w; h.w = x > 0.f ? x : expm1f(x);
    *(float4*)&out[i] = h;
}

// ---------------- launch ----------------
extern "C" void kernel_launch(void* const* d_in, const int* in_sizes, int n_in,
                              void* d_out, int out_size) {
    const float* data  = (const float*)d_in[0];
    const int*   neigh = (const int*)d_in[1];
    const float* w1 = (const float*)d_in[2];
    const float* g1 = (const float*)d_in[3];
    const float* b1 = (const float*)d_in[4];
    const float* w3 = (const float*)d_in[5];
    const float* g3 = (const float*)d_in[6];
    const float* b3 = (const float*)d_in[7];
    const float* w2 = (const float*)d_in[8];
    const float* g2 = (const float*)d_in[9];
    const float* b2 = (const float*)d_in[10];
    float* out = (float*)d_out;

    const int n = in_sizes[0] / C_IN;
    const float inv_n = 1.0f / (float)n;
    const int nblk128 = (n + 127) / 128;
    const long long tot_b = (long long)n * C_B;
    const long long tot_c = (long long)n * C_IN;

    cudaFuncSetAttribute(gemm1_mma_kernel,
                         cudaFuncAttributeMaxDynamicSharedMemorySize, G1_SMEM);
    cudaFuncSetAttribute(octconv_mma_kernel,
                         cudaFuncAttributeMaxDynamicSharedMemorySize, OCT_SMEM);
    cudaFuncSetAttribute(gemm2_mma_kernel,
                         cudaFuncAttributeMaxDynamicSharedMemorySize, G2_SMEM);

    zero_stats_kernel<<<1, 256>>>();
    w3_split_kernel<<<(K_TAP * C_B * C_B + 255) / 256, 256>>>(w3);

    gemm1_mma_kernel<<<nblk128, 256, G1_SMEM>>>(data, w1, n);
    stats1_kernel<<<512, 256>>>(n);
    bnfin1_kernel<<<1, C_B>>>(g1, b1, inv_n);
    act1_split_kernel<<<(int)((tot_b / 4 + 255) / 256), 256>>>(tot_b);

    octconv_mma_kernel<<<nblk128, 256, OCT_SMEM>>>(neigh, n);
    stats2_kernel<<<512, 256>>>(n);
    bnfin2_kernel<<<1, C_B>>>(g3, b3, inv_n);

    gemm2_mma_kernel<<<dim3(nblk128, 2), 256, G2_SMEM>>>(w2, n);
    stats3_kernel<<<512, 256>>>(n);
    bnfin3_kernel<<<1, C_IN>>>(g2, b2, inv_n);

    final_kernel<<<(int)((tot_c / 4 + 255) / 256), 256>>>(data, out, tot_c);
}